// round 14
// baseline (speedup 1.0000x reference)
#include <cuda_runtime.h>

#define HIDDEN 51
#define JP 64
#define KH 26            // k-rows per half (52 rows; rows beyond 50 are zero)
#define L_SEQ 1000
#define NBLK 128
#define THREADS 128      // 1 group; 8 batches as 2 sets of 4; 1 warp/SMSP

typedef unsigned long long ull;

// Preprocessed weights (gate-interleaved): [k=0..51][j=0..63] -> (i,f,g,o)
__device__ float4 g_U4[2 * KH * JP];
__device__ float4 g_W4[JP];   // x weights per j, gates interleaved
__device__ float4 g_B4[JP];   // W_b + U_b per j, gates interleaved
__device__ float  g_L[JP];    // lin_w per j

// ---------- f32x2 helpers (exact packed fp32) ----------
__device__ __forceinline__ ull pk2(float lo, float hi) {
    ull r; asm("mov.b64 %0, {%1, %2};" : "=l"(r) : "f"(lo), "f"(hi)); return r;
}
__device__ __forceinline__ void up2(float& lo, float& hi, ull v) {
    asm("mov.b64 {%0, %1}, %2;" : "=f"(lo), "=f"(hi) : "l"(v));
}
__device__ __forceinline__ ull f2fma(ull a, ull b, ull c) {
    ull d; asm("fma.rn.f32x2 %0, %1, %2, %3;" : "=l"(d) : "l"(a), "l"(b), "l"(c)); return d;
}
__device__ __forceinline__ ull f2add(ull a, ull b) {
    ull d; asm("add.rn.f32x2 %0, %1, %2;" : "=l"(d) : "l"(a), "l"(b)); return d;
}
// accurate fast tanh: 1 - 2/(exp(2x)+1); saturates correctly at +-inf
__device__ __forceinline__ float fast_tanh(float xv) {
    float e;
    asm("ex2.approx.f32 %0, %1;" : "=f"(e) : "f"(xv * 2.8853900817779268f));
    float r;
    asm("rcp.approx.f32 %0, %1;" : "=f"(r) : "f"(e + 1.0f));
    return fmaf(-2.0f, r, 1.0f);
}

// ---------- prep: reorder weights into gate-interleaved padded layout ----------
__global__ void prep_kernel(const float* __restrict__ W_w, const float* __restrict__ W_b,
                            const float* __restrict__ U_w, const float* __restrict__ U_b,
                            const float* __restrict__ lin_w) {
    int i = blockIdx.x * 128 + threadIdx.x;   // 0 .. 3327
    int k = i >> 6, j = i & 63;
    float4 u = make_float4(0.f, 0.f, 0.f, 0.f);
    if (k < HIDDEN && j < HIDDEN) {
        u.x = U_w[(0 * HIDDEN + j) * HIDDEN + k];
        u.y = U_w[(1 * HIDDEN + j) * HIDDEN + k];
        u.z = U_w[(2 * HIDDEN + j) * HIDDEN + k];
        u.w = U_w[(3 * HIDDEN + j) * HIDDEN + k];
    }
    g_U4[i] = u;
    if (i < JP) {
        float4 w = make_float4(0.f, 0.f, 0.f, 0.f);
        float4 b = make_float4(0.f, 0.f, 0.f, 0.f);
        float lw = 0.f;
        if (i < HIDDEN) {
            w.x = W_w[0 * HIDDEN + i]; w.y = W_w[1 * HIDDEN + i];
            w.z = W_w[2 * HIDDEN + i]; w.w = W_w[3 * HIDDEN + i];
            b.x = W_b[0 * HIDDEN + i] + U_b[0 * HIDDEN + i];
            b.y = W_b[1 * HIDDEN + i] + U_b[1 * HIDDEN + i];
            b.z = W_b[2 * HIDDEN + i] + U_b[2 * HIDDEN + i];
            b.w = W_b[3 * HIDDEN + i] + U_b[3 * HIDDEN + i];
            lw = lin_w[i];
        }
        g_W4[i] = w; g_B4[i] = b; g_L[i] = lw;
    }
}

// ---------- main: 2-set software pipeline fused in the SAME warps ----------
// 128 threads = (half, j) exactly like R2; 8 batches as sets S0 (0-3), S1 (4-7).
// Interval: [ A(set a, t) ; B(set b, t') ] ; __syncthreads().
// B's serial chain hides inside A's fma stream of the SAME thread (ILP).

// A phase for set SA at time TA: partial gates -> psum[SA]
#define APART(SA, TA)                                                            \
    {                                                                            \
        const int tA_ = (TA);                                                    \
        ull a_if[4], a_go[4];                                                    \
        _Pragma("unroll")                                                        \
        for (int q = 0; q < 4; q++) {                                            \
            float xv = x_sh[(SA) * 4 + q][tA_];                                  \
            ull x2 = pk2(xv, xv);                                                \
            a_if[q] = (half == 0) ? f2fma(x2, w_if, b_if) : pk2(0.f, 0.f);       \
            a_go[q] = (half == 0) ? f2fma(x2, w_go, b_go) : pk2(0.f, 0.f);       \
        }                                                                        \
        _Pragma("unroll")                                                        \
        for (int kk = 0; kk < KH; kk++) {                                        \
            float4 hq = *(const float4*)&h_sh[SA][half * KH + kk][0];            \
            ull h0 = pk2(hq.x, hq.x), h1 = pk2(hq.y, hq.y);                      \
            ull h2 = pk2(hq.z, hq.z), h3 = pk2(hq.w, hq.w);                      \
            a_if[0] = f2fma(h0, u_if[kk], a_if[0]);                              \
            a_go[0] = f2fma(h0, u_go[kk], a_go[0]);                              \
            a_if[1] = f2fma(h1, u_if[kk], a_if[1]);                              \
            a_go[1] = f2fma(h1, u_go[kk], a_go[1]);                              \
            a_if[2] = f2fma(h2, u_if[kk], a_if[2]);                              \
            a_go[2] = f2fma(h2, u_go[kk], a_go[2]);                              \
            a_if[3] = f2fma(h3, u_if[kk], a_if[3]);                              \
            a_go[3] = f2fma(h3, u_go[kk], a_go[3]);                              \
        }                                                                        \
        _Pragma("unroll")                                                        \
        for (int q = 0; q < 4; q++) {                                            \
            ulonglong2 v; v.x = a_if[q]; v.y = a_go[q];                          \
            *(ulonglong2*)&psum[SA][half][q][j] = v;                             \
        }                                                                        \
    }

// B phase for set SB at time TB: lagged out store, combine psum, update c/h, redp
#define BPART(SB, TB)                                                            \
    {                                                                            \
        const int tB_ = (TB);                                                    \
        if (tB_ >= 1 && tid < 4) {                                               \
            int b = tid, pb = (tB_ - 1) & 1;                                     \
            int wbase = (b >> 1) << 1;                                           \
            out[(b0 + (SB) * 4 + b) * L_SEQ + (tB_ - 1)] =                       \
                redp[SB][pb][wbase][b & 1] + redp[SB][pb][wbase + 1][b & 1] + lbv;\
        }                                                                        \
        float prod0, prod1;                                                      \
        {                                                                        \
            int b = half * 2 + 0;                                                \
            ulonglong2 p0 = *(const ulonglong2*)&psum[SB][0][b][j];              \
            ulonglong2 p1 = *(const ulonglong2*)&psum[SB][1][b][j];              \
            ull s_if = f2add(p0.x, p1.x), s_go = f2add(p0.y, p1.y);              \
            float gi, gf, gg, go;                                                \
            up2(gi, gf, s_if); up2(gg, go, s_go);                                \
            c[SB][0] = fmaf(gf, c[SB][0], gi * gg);  /* faithful: no sigmoids */ \
            float h = go * fast_tanh(c[SB][0]);                                  \
            h_sh[SB][j][b] = h;                                                  \
            prod0 = h * lw;                                                      \
        }                                                                        \
        {                                                                        \
            int b = half * 2 + 1;                                                \
            ulonglong2 p0 = *(const ulonglong2*)&psum[SB][0][b][j];              \
            ulonglong2 p1 = *(const ulonglong2*)&psum[SB][1][b][j];              \
            ull s_if = f2add(p0.x, p1.x), s_go = f2add(p0.y, p1.y);              \
            float gi, gf, gg, go;                                                \
            up2(gi, gf, s_if); up2(gg, go, s_go);                                \
            c[SB][1] = fmaf(gf, c[SB][1], gi * gg);                              \
            float h = go * fast_tanh(c[SB][1]);                                  \
            h_sh[SB][j][b] = h;                                                  \
            prod1 = h * lw;                                                      \
        }                                                                        \
        _Pragma("unroll")                                                        \
        for (int off = 16; off >= 1; off >>= 1) {                                \
            prod0 += __shfl_xor_sync(0xffffffffu, prod0, off);                   \
            prod1 += __shfl_xor_sync(0xffffffffu, prod1, off);                   \
        }                                                                        \
        if (lane == 0) {                                                         \
            redp[SB][tB_ & 1][w][0] = prod0;                                     \
            redp[SB][tB_ & 1][w][1] = prod1;                                     \
        }                                                                        \
    }

__global__ void __launch_bounds__(THREADS, 1)
lstm_main(const float* __restrict__ x, const float* __restrict__ lin_b,
          float* __restrict__ out) {
    __shared__ float x_sh[8][L_SEQ];                         // all x for my 8 batches (32 KB)
    __shared__ __align__(16) float  h_sh[2][JP][4];          // [set][unit][batch-in-set]
    __shared__ __align__(16) float4 psum[2][2][4][JP];       // [set][half][batch][j]
    __shared__ float redp[2][2][4][2];                       // [set][t&1][warp][slot]

    const int tid  = threadIdx.x;
    const int half = tid >> 6;
    const int j    = tid & 63;
    const int lane = tid & 31;
    const int w    = tid >> 5;        // warp 0..3
    const int b0   = blockIdx.x * 8;

    // Register-resident U rows (gate-packed pairs): 104 regs, cap 512 @128thr
    ull u_if[KH], u_go[KH];
#pragma unroll
    for (int kk = 0; kk < KH; kk++) {
        float4 u = g_U4[(half * KH + kk) * JP + j];
        u_if[kk] = pk2(u.x, u.y);
        u_go[kk] = pk2(u.z, u.w);
    }
    float4 wv = g_W4[j], bv = g_B4[j];
    const ull w_if = pk2(wv.x, wv.y), w_go = pk2(wv.z, wv.w);
    const ull b_if = pk2(bv.x, bv.y), b_go = pk2(bv.z, bv.w);
    const float lw  = g_L[j];
    const float lbv = lin_b[0];

    // cell state: [set][batch-in-pair] — constant-indexed (set literal in macros)
    float c[2][2] = {{0.f, 0.f}, {0.f, 0.f}};

    // preload ALL x into smem (coalesced), zero h
    for (int i = tid; i < 8 * L_SEQ; i += THREADS) {
        int b = i / L_SEQ, tt = i - b * L_SEQ;
        x_sh[b][tt] = x[(b0 + b) * L_SEQ + tt];
    }
    for (int i = tid; i < 2 * JP * 4; i += THREADS) ((float*)h_sh)[i] = 0.f;
    __syncthreads();

    // prologue
    APART(0, 0)
    __syncthreads();

#pragma unroll 1
    for (int t = 0; t < L_SEQ - 1; ++t) {
        APART(1, t)
        BPART(0, t)
        __syncthreads();
        APART(0, t + 1)
        BPART(1, t)
        __syncthreads();
    }
    // epilogue: t = L-1
    APART(1, L_SEQ - 1)
    BPART(0, L_SEQ - 1)
    __syncthreads();
    BPART(1, L_SEQ - 1)
    __syncthreads();

    // flush outputs for t = L-1, both sets
    if (tid < 8) {
        int s = tid >> 2, b = tid & 3, pb = (L_SEQ - 1) & 1;
        int wbase = (b >> 1) << 1;
        out[(b0 + s * 4 + b) * L_SEQ + (L_SEQ - 1)] =
            redp[s][pb][wbase][b & 1] + redp[s][pb][wbase + 1][b & 1] + lbv;
    }
}

extern "C" void kernel_launch(void* const* d_in, const int* in_sizes, int n_in,
                              void* d_out, int out_size) {
    (void)in_sizes; (void)n_in; (void)out_size;
    const float* x     = (const float*)d_in[0];
    const float* W_w   = (const float*)d_in[1];
    const float* W_b   = (const float*)d_in[2];
    const float* U_w   = (const float*)d_in[3];
    const float* U_b   = (const float*)d_in[4];
    const float* lin_w = (const float*)d_in[5];
    const float* lin_b = (const float*)d_in[6];
    // d_in[7] = future (static 0) — ignored.

    prep_kernel<<<26, 128>>>(W_w, W_b, U_w, U_b, lin_w);
    lstm_main<<<NBLK, THREADS>>>(x, lin_b, (float*)d_out);
}

// round 15
// speedup vs baseline: 1.2818x; 1.2818x over previous
#include <cuda_runtime.h>

#define HIDDEN 51
#define JP 64
#define KH 26            // k-rows per half
#define L_SEQ 1000
#define NBLK 128
#define NBG 4            // batches per group
#define THREADS 256      // 2 groups x 128 (4 warps each)

typedef unsigned long long ull;

// Preprocessed weights (gate-interleaved): [k=0..51][j=0..63] -> (i,f,g,o)
__device__ float4 g_U4[2 * KH * JP];
__device__ float4 g_W4[JP];   // x weights per j, gates interleaved
__device__ float4 g_B4[JP];   // W_b + U_b per j, gates interleaved
__device__ float  g_L[JP];    // lin_w per j

// ---------- f32x2 helpers (exact packed fp32) ----------
__device__ __forceinline__ ull pk2(float lo, float hi) {
    ull r; asm("mov.b64 %0, {%1, %2};" : "=l"(r) : "f"(lo), "f"(hi)); return r;
}
__device__ __forceinline__ void up2(float& lo, float& hi, ull v) {
    asm("mov.b64 {%0, %1}, %2;" : "=f"(lo), "=f"(hi) : "l"(v));
}
__device__ __forceinline__ ull f2fma(ull a, ull b, ull c) {
    ull d; asm("fma.rn.f32x2 %0, %1, %2, %3;" : "=l"(d) : "l"(a), "l"(b), "l"(c)); return d;
}
__device__ __forceinline__ ull f2add(ull a, ull b) {
    ull d; asm("add.rn.f32x2 %0, %1, %2;" : "=l"(d) : "l"(a), "l"(b)); return d;
}
__device__ __forceinline__ ull shfl_xor64(ull v, int m) {
    unsigned lo, hi;
    asm("mov.b64 {%0,%1}, %2;" : "=r"(lo), "=r"(hi) : "l"(v));
    lo = __shfl_xor_sync(0xffffffffu, lo, m);
    hi = __shfl_xor_sync(0xffffffffu, hi, m);
    ull r; asm("mov.b64 %0, {%1,%2};" : "=l"(r) : "r"(lo), "r"(hi));
    return r;
}
// accurate fast tanh: 1 - 2/(exp(2x)+1); saturates correctly at +-inf
__device__ __forceinline__ float fast_tanh(float xv) {
    float e;
    asm("ex2.approx.f32 %0, %1;" : "=f"(e) : "f"(xv * 2.8853900817779268f));
    float r;
    asm("rcp.approx.f32 %0, %1;" : "=f"(r) : "f"(e + 1.0f));
    return fmaf(-2.0f, r, 1.0f);
}
__device__ __forceinline__ void group_bar(int barid) {
    asm volatile("bar.sync %0, %1;" :: "r"(barid), "r"(128) : "memory");
}

// ---------- prep: reorder weights into gate-interleaved padded layout ----------
__global__ void prep_kernel(const float* __restrict__ W_w, const float* __restrict__ W_b,
                            const float* __restrict__ U_w, const float* __restrict__ U_b,
                            const float* __restrict__ lin_w) {
    int i = blockIdx.x * 128 + threadIdx.x;   // 0 .. 3327
    int k = i >> 6, j = i & 63;
    float4 u = make_float4(0.f, 0.f, 0.f, 0.f);
    if (k < HIDDEN && j < HIDDEN) {
        u.x = U_w[(0 * HIDDEN + j) * HIDDEN + k];
        u.y = U_w[(1 * HIDDEN + j) * HIDDEN + k];
        u.z = U_w[(2 * HIDDEN + j) * HIDDEN + k];
        u.w = U_w[(3 * HIDDEN + j) * HIDDEN + k];
    }
    g_U4[i] = u;
    if (i < JP) {
        float4 w = make_float4(0.f, 0.f, 0.f, 0.f);
        float4 b = make_float4(0.f, 0.f, 0.f, 0.f);
        float lw = 0.f;
        if (i < HIDDEN) {
            w.x = W_w[0 * HIDDEN + i]; w.y = W_w[1 * HIDDEN + i];
            w.z = W_w[2 * HIDDEN + i]; w.w = W_w[3 * HIDDEN + i];
            b.x = W_b[0 * HIDDEN + i] + U_b[0 * HIDDEN + i];
            b.y = W_b[1 * HIDDEN + i] + U_b[1 * HIDDEN + i];
            b.z = W_b[2 * HIDDEN + i] + U_b[2 * HIDDEN + i];
            b.w = W_b[3 * HIDDEN + i] + U_b[3 * HIDDEN + i];
            lw = lin_w[i];
        }
        g_W4[i] = w; g_B4[i] = b; g_L[i] = lw;
    }
}

// ---------- main ----------
// 256 threads = 2 groups x 128 (4 warps). Lane = hf*16 + j16; j = warp*16 + j16.
// Both k-halves of unit j live in ONE warp -> half-combine is a single xor-16
// shuffle exchange. No psum smem. ONE barrier per step (double-buffered h).
__global__ void __launch_bounds__(THREADS, 1)
lstm_main(const float* __restrict__ x, const float* __restrict__ lin_b,
          float* __restrict__ out) {
    __shared__ __align__(16) float h_sh[2][2][JP][NBG];   // [group][buf][unit][batch]
    __shared__ float redp[2][2][4][4];                    // [group][parity][warp][batch]

    const int tid  = threadIdx.x;
    const int g    = tid >> 7;
    const int gtid = tid & 127;
    const int lane = tid & 31;
    const int w    = gtid >> 5;        // warp within group (0..3)
    const int hf   = lane >> 4;        // k-half (IN-WARP)
    const int j16  = lane & 15;
    const int j    = w * 16 + j16;     // hidden unit
    const int b0   = blockIdx.x * 8 + g * NBG;

    // Register-resident U rows for (hf, j): 26 x {(i,f),(g,o)} pairs (104 regs)
    ull u_if[KH], u_go[KH];
#pragma unroll
    for (int kk = 0; kk < KH; kk++) {
        float4 u = g_U4[(hf * KH + kk) * JP + j];
        u_if[kk] = pk2(u.x, u.y);
        u_go[kk] = pk2(u.z, u.w);
    }
    float4 wv = g_W4[j], bv = g_B4[j];
    const ull w_if = pk2(wv.x, wv.y), w_go = pk2(wv.z, wv.w);
    const ull b_if = pk2(bv.x, bv.y), b_go = pk2(bv.z, bv.w);
    const float lw  = g_L[j];
    const float lbv = lin_b[0];

    // cell state for my 2 owned batches (b = hf*2 + s)
    float c0 = 0.f, c1 = 0.f;

    // zero h (both buffers)
    for (int i = tid; i < 2 * 2 * JP * NBG; i += THREADS) ((float*)h_sh)[i] = 0.f;

    // preload x for t=0 (4 batches of my group)
    float xq[NBG];
#pragma unroll
    for (int q = 0; q < NBG; q++) xq[q] = x[(b0 + q) * L_SEQ + 0];

    __syncthreads();

    for (int t = 0; t < L_SEQ; ++t) {
        const int rb = t & 1, wb = rb ^ 1;

        // ---- lagged output store for step t-1 (pre-bar read; epoch-safe) ----
        if (t > 0 && gtid < NBG) {
            int b = gtid, pb = (t - 1) & 1;
            out[(b0 + b) * L_SEQ + (t - 1)] =
                redp[g][pb][0][b] + redp[g][pb][1][b] +
                redp[g][pb][2][b] + redp[g][pb][3][b] + lbv;
        }

        // ---- phase A: partial gates for 4 batches over my k-half ----
        ull aif0, aif1, aif2, aif3, ago0, ago1, ago2, ago3;
        {
            ull x20 = pk2(xq[0], xq[0]), x21 = pk2(xq[1], xq[1]);
            ull x22 = pk2(xq[2], xq[2]), x23 = pk2(xq[3], xq[3]);
            ull z = pk2(0.f, 0.f);
            aif0 = (hf == 0) ? f2fma(x20, w_if, b_if) : z;
            ago0 = (hf == 0) ? f2fma(x20, w_go, b_go) : z;
            aif1 = (hf == 0) ? f2fma(x21, w_if, b_if) : z;
            ago1 = (hf == 0) ? f2fma(x21, w_go, b_go) : z;
            aif2 = (hf == 0) ? f2fma(x22, w_if, b_if) : z;
            ago2 = (hf == 0) ? f2fma(x22, w_go, b_go) : z;
            aif3 = (hf == 0) ? f2fma(x23, w_if, b_if) : z;
            ago3 = (hf == 0) ? f2fma(x23, w_go, b_go) : z;
        }
#pragma unroll
        for (int kk = 0; kk < KH; kk++) {
            float4 hq = *(const float4*)&h_sh[g][rb][hf * KH + kk][0];
            ull h0 = pk2(hq.x, hq.x), h1 = pk2(hq.y, hq.y);
            ull h2 = pk2(hq.z, hq.z), h3 = pk2(hq.w, hq.w);
            aif0 = f2fma(h0, u_if[kk], aif0); ago0 = f2fma(h0, u_go[kk], ago0);
            aif1 = f2fma(h1, u_if[kk], aif1); ago1 = f2fma(h1, u_go[kk], ago1);
            aif2 = f2fma(h2, u_if[kk], aif2); ago2 = f2fma(h2, u_go[kk], ago2);
            aif3 = f2fma(h3, u_if[kk], aif3); ago3 = f2fma(h3, u_go[kk], ago3);
        }

        // prefetch next x (hidden under exchange/update)
        float xn[NBG];
        {
            int tn = (t + 1 < L_SEQ) ? t + 1 : t;
#pragma unroll
            for (int q = 0; q < NBG; q++) xn[q] = x[(b0 + q) * L_SEQ + tn];
        }

        // ---- in-warp half-combine: single xor-16 exchange ----
        // I own batches hf*2+{0,1}; send partials for the partner's batches.
        ull snd_if0 = hf ? aif0 : aif2, snd_if1 = hf ? aif1 : aif3;
        ull snd_go0 = hf ? ago0 : ago2, snd_go1 = hf ? ago1 : ago3;
        ull own_if0 = hf ? aif2 : aif0, own_if1 = hf ? aif3 : aif1;
        ull own_go0 = hf ? ago2 : ago0, own_go1 = hf ? ago3 : ago1;
        ull s_if0 = f2add(own_if0, shfl_xor64(snd_if0, 16));
        ull s_if1 = f2add(own_if1, shfl_xor64(snd_if1, 16));
        ull s_go0 = f2add(own_go0, shfl_xor64(snd_go0, 16));
        ull s_go1 = f2add(own_go1, shfl_xor64(snd_go1, 16));

        // ---- update c/h for (j, batches hf*2, hf*2+1) ----
        float prod0, prod1;
        {
            float gi, gf, gg, go;
            up2(gi, gf, s_if0); up2(gg, go, s_go0);
            c0 = fmaf(gf, c0, gi * gg);            // faithful: no sigmoids
            float h = go * fast_tanh(c0);
            h_sh[g][wb][j][hf * 2 + 0] = h;
            prod0 = h * lw;
        }
        {
            float gi, gf, gg, go;
            up2(gi, gf, s_if1); up2(gg, go, s_go1);
            c1 = fmaf(gf, c1, gi * gg);
            float h = go * fast_tanh(c1);
            h_sh[g][wb][j][hf * 2 + 1] = h;
            prod1 = h * lw;
        }

        // ---- output partials: reduce over j16 within my half-warp ----
        prod0 += __shfl_xor_sync(0xffffffffu, prod0, 1);
        prod1 += __shfl_xor_sync(0xffffffffu, prod1, 1);
        prod0 += __shfl_xor_sync(0xffffffffu, prod0, 2);
        prod1 += __shfl_xor_sync(0xffffffffu, prod1, 2);
        prod0 += __shfl_xor_sync(0xffffffffu, prod0, 4);
        prod1 += __shfl_xor_sync(0xffffffffu, prod1, 4);
        prod0 += __shfl_xor_sync(0xffffffffu, prod0, 8);
        prod1 += __shfl_xor_sync(0xffffffffu, prod1, 8);
        if (j16 == 0) {
            redp[g][t & 1][w][hf * 2 + 0] = prod0;
            redp[g][t & 1][w][hf * 2 + 1] = prod1;
        }

#pragma unroll
        for (int q = 0; q < NBG; q++) xq[q] = xn[q];

        group_bar(g + 1);   // the ONLY barrier per step
    }

    // ---- tail: flush output for the final step ----
    if (gtid < NBG) {
        int b = gtid, pb = (L_SEQ - 1) & 1;
        out[(b0 + b) * L_SEQ + (L_SEQ - 1)] =
            redp[g][pb][0][b] + redp[g][pb][1][b] +
            redp[g][pb][2][b] + redp[g][pb][3][b] + lbv;
    }
}

extern "C" void kernel_launch(void* const* d_in, const int* in_sizes, int n_in,
                              void* d_out, int out_size) {
    (void)in_sizes; (void)n_in; (void)out_size;
    const float* x     = (const float*)d_in[0];
    const float* W_w   = (const float*)d_in[1];
    const float* W_b   = (const float*)d_in[2];
    const float* U_w   = (const float*)d_in[3];
    const float* U_b   = (const float*)d_in[4];
    const float* lin_w = (const float*)d_in[5];
    const float* lin_b = (const float*)d_in[6];
    // d_in[7] = future (static 0) — ignored.

    prep_kernel<<<26, 128>>>(W_w, W_b, U_w, U_b, lin_w);
    lstm_main<<<NBLK, THREADS>>>(x, lin_b, (float*)d_out);
}

// round 16
// speedup vs baseline: 1.3111x; 1.0229x over previous
#include <cuda_runtime.h>

#define HIDDEN 51
#define JP 64
#define KH 26            // k-rows per half
#define L_SEQ 1000
#define NBLK 128
#define NBG 4            // batches per group
#define THREADS 256      // 2 groups x 128 (4 warps each)

typedef unsigned long long ull;

// Preprocessed weights (gate-interleaved): [k=0..51][j=0..63] -> (i,f,g,o)
__device__ float4 g_U4[2 * KH * JP];
__device__ float4 g_W4[JP];   // x weights per j, gates interleaved
__device__ float4 g_B4[JP];   // W_b + U_b per j, gates interleaved
__device__ float  g_L[JP];    // lin_w per j

// ---------- f32x2 helpers (exact packed fp32) ----------
__device__ __forceinline__ ull pk2(float lo, float hi) {
    ull r; asm("mov.b64 %0, {%1, %2};" : "=l"(r) : "f"(lo), "f"(hi)); return r;
}
__device__ __forceinline__ void up2(float& lo, float& hi, ull v) {
    asm("mov.b64 {%0, %1}, %2;" : "=f"(lo), "=f"(hi) : "l"(v));
}
__device__ __forceinline__ ull f2fma(ull a, ull b, ull c) {
    ull d; asm("fma.rn.f32x2 %0, %1, %2, %3;" : "=l"(d) : "l"(a), "l"(b), "l"(c)); return d;
}
__device__ __forceinline__ ull f2add(ull a, ull b) {
    ull d; asm("add.rn.f32x2 %0, %1, %2;" : "=l"(d) : "l"(a), "l"(b)); return d;
}
__device__ __forceinline__ ull shfl_xor64(ull v, int m) {
    unsigned lo, hi;
    asm("mov.b64 {%0,%1}, %2;" : "=r"(lo), "=r"(hi) : "l"(v));
    lo = __shfl_xor_sync(0xffffffffu, lo, m);
    hi = __shfl_xor_sync(0xffffffffu, hi, m);
    ull r; asm("mov.b64 %0, {%1,%2};" : "=l"(r) : "r"(lo), "r"(hi));
    return r;
}
// accurate fast tanh: 1 - 2/(exp(2x)+1); saturates correctly at +-inf
__device__ __forceinline__ float fast_tanh(float xv) {
    float e;
    asm("ex2.approx.f32 %0, %1;" : "=f"(e) : "f"(xv * 2.8853900817779268f));
    float r;
    asm("rcp.approx.f32 %0, %1;" : "=f"(r) : "f"(e + 1.0f));
    return fmaf(-2.0f, r, 1.0f);
}
__device__ __forceinline__ void group_bar(int barid) {
    asm volatile("bar.sync %0, %1;" :: "r"(barid), "r"(128) : "memory");
}

// ---------- prep: reorder weights into gate-interleaved padded layout ----------
__global__ void prep_kernel(const float* __restrict__ W_w, const float* __restrict__ W_b,
                            const float* __restrict__ U_w, const float* __restrict__ U_b,
                            const float* __restrict__ lin_w) {
    int i = blockIdx.x * 128 + threadIdx.x;   // 0 .. 3327
    int k = i >> 6, j = i & 63;
    float4 u = make_float4(0.f, 0.f, 0.f, 0.f);
    if (k < HIDDEN && j < HIDDEN) {
        u.x = U_w[(0 * HIDDEN + j) * HIDDEN + k];
        u.y = U_w[(1 * HIDDEN + j) * HIDDEN + k];
        u.z = U_w[(2 * HIDDEN + j) * HIDDEN + k];
        u.w = U_w[(3 * HIDDEN + j) * HIDDEN + k];
    }
    g_U4[i] = u;
    if (i < JP) {
        float4 w = make_float4(0.f, 0.f, 0.f, 0.f);
        float4 b = make_float4(0.f, 0.f, 0.f, 0.f);
        float lw = 0.f;
        if (i < HIDDEN) {
            w.x = W_w[0 * HIDDEN + i]; w.y = W_w[1 * HIDDEN + i];
            w.z = W_w[2 * HIDDEN + i]; w.w = W_w[3 * HIDDEN + i];
            b.x = W_b[0 * HIDDEN + i] + U_b[0 * HIDDEN + i];
            b.y = W_b[1 * HIDDEN + i] + U_b[1 * HIDDEN + i];
            b.z = W_b[2 * HIDDEN + i] + U_b[2 * HIDDEN + i];
            b.w = W_b[3 * HIDDEN + i] + U_b[3 * HIDDEN + i];
            lw = lin_w[i];
        }
        g_W4[i] = w; g_B4[i] = b; g_L[i] = lw;
    }
}

// ---------- main ----------
// 256 threads = 2 groups x 128 (4 warps). Lane = hf*16 + j16; j = warp*16 + j16.
// Both k-halves of unit j live in ONE warp -> half-combine is a single xor-16
// shuffle exchange. No psum smem. ONE barrier per step (double-buffered h).
// R16: output shuffle-reduction + redp write moved AFTER the barrier (overlaps
// next step's phase A); out store lagged 2 steps (ordering via bar parity).
__global__ void __launch_bounds__(THREADS, 1)
lstm_main(const float* __restrict__ x, const float* __restrict__ lin_b,
          float* __restrict__ out) {
    __shared__ __align__(16) float h_sh[2][2][JP][NBG];   // [group][buf][unit][batch]
    __shared__ float redp[2][2][4][4];                    // [group][parity][warp][batch]

    const int tid  = threadIdx.x;
    const int g    = tid >> 7;
    const int gtid = tid & 127;
    const int lane = tid & 31;
    const int w    = gtid >> 5;        // warp within group (0..3)
    const int hf   = lane >> 4;        // k-half (IN-WARP)
    const int j16  = lane & 15;
    const int j    = w * 16 + j16;     // hidden unit
    const int b0   = blockIdx.x * 8 + g * NBG;

    // Register-resident U rows for (hf, j): 26 x {(i,f),(g,o)} pairs (104 regs)
    ull u_if[KH], u_go[KH];
#pragma unroll
    for (int kk = 0; kk < KH; kk++) {
        float4 u = g_U4[(hf * KH + kk) * JP + j];
        u_if[kk] = pk2(u.x, u.y);
        u_go[kk] = pk2(u.z, u.w);
    }
    float4 wv = g_W4[j], bv = g_B4[j];
    const ull w_if = pk2(wv.x, wv.y), w_go = pk2(wv.z, wv.w);
    const ull b_if = pk2(bv.x, bv.y), b_go = pk2(bv.z, bv.w);
    const float lw  = g_L[j];
    const float lbv = lin_b[0];

    // cell state for my 2 owned batches (b = hf*2 + s)
    float c0 = 0.f, c1 = 0.f;

    // zero h (both buffers)
    for (int i = tid; i < 2 * 2 * JP * NBG; i += THREADS) ((float*)h_sh)[i] = 0.f;

    // preload x for t=0 (4 batches of my group)
    float xq[NBG];
#pragma unroll
    for (int q = 0; q < NBG; q++) xq[q] = x[(b0 + q) * L_SEQ + 0];

    __syncthreads();

    for (int t = 0; t < L_SEQ; ++t) {
        const int rb = t & 1, wb = rb ^ 1;

        // ---- lag-2 output store for step t-2 (pre-bar read; epoch-safe:
        //      redp(t-2) was written post-bar(t-2); bar(t-1) orders it) ----
        if (t >= 2 && gtid < NBG) {
            int b = gtid, pb = t & 1;     // (t-2)&1 == t&1
            out[(b0 + b) * L_SEQ + (t - 2)] =
                redp[g][pb][0][b] + redp[g][pb][1][b] +
                redp[g][pb][2][b] + redp[g][pb][3][b] + lbv;
        }

        // ---- phase A: partial gates for 4 batches over my k-half ----
        ull aif0, aif1, aif2, aif3, ago0, ago1, ago2, ago3;
        {
            ull x20 = pk2(xq[0], xq[0]), x21 = pk2(xq[1], xq[1]);
            ull x22 = pk2(xq[2], xq[2]), x23 = pk2(xq[3], xq[3]);
            ull z = pk2(0.f, 0.f);
            aif0 = (hf == 0) ? f2fma(x20, w_if, b_if) : z;
            ago0 = (hf == 0) ? f2fma(x20, w_go, b_go) : z;
            aif1 = (hf == 0) ? f2fma(x21, w_if, b_if) : z;
            ago1 = (hf == 0) ? f2fma(x21, w_go, b_go) : z;
            aif2 = (hf == 0) ? f2fma(x22, w_if, b_if) : z;
            ago2 = (hf == 0) ? f2fma(x22, w_go, b_go) : z;
            aif3 = (hf == 0) ? f2fma(x23, w_if, b_if) : z;
            ago3 = (hf == 0) ? f2fma(x23, w_go, b_go) : z;
        }
#pragma unroll
        for (int kk = 0; kk < KH; kk++) {
            float4 hq = *(const float4*)&h_sh[g][rb][hf * KH + kk][0];
            ull h0 = pk2(hq.x, hq.x), h1 = pk2(hq.y, hq.y);
            ull h2 = pk2(hq.z, hq.z), h3 = pk2(hq.w, hq.w);
            aif0 = f2fma(h0, u_if[kk], aif0); ago0 = f2fma(h0, u_go[kk], ago0);
            aif1 = f2fma(h1, u_if[kk], aif1); ago1 = f2fma(h1, u_go[kk], ago1);
            aif2 = f2fma(h2, u_if[kk], aif2); ago2 = f2fma(h2, u_go[kk], ago2);
            aif3 = f2fma(h3, u_if[kk], aif3); ago3 = f2fma(h3, u_go[kk], ago3);
        }

        // prefetch next x (hidden under exchange/update)
        float xn[NBG];
        {
            int tn = (t + 1 < L_SEQ) ? t + 1 : t;
#pragma unroll
            for (int q = 0; q < NBG; q++) xn[q] = x[(b0 + q) * L_SEQ + tn];
        }

        // ---- in-warp half-combine: single xor-16 exchange ----
        ull snd_if0 = hf ? aif0 : aif2, snd_if1 = hf ? aif1 : aif3;
        ull snd_go0 = hf ? ago0 : ago2, snd_go1 = hf ? ago1 : ago3;
        ull own_if0 = hf ? aif2 : aif0, own_if1 = hf ? aif3 : aif1;
        ull own_go0 = hf ? ago2 : ago0, own_go1 = hf ? ago3 : ago1;
        ull s_if0 = f2add(own_if0, shfl_xor64(snd_if0, 16));
        ull s_if1 = f2add(own_if1, shfl_xor64(snd_if1, 16));
        ull s_go0 = f2add(own_go0, shfl_xor64(snd_go0, 16));
        ull s_go1 = f2add(own_go1, shfl_xor64(snd_go1, 16));

        // ---- update c/h for (j, batches hf*2, hf*2+1) ----
        float prod0, prod1;
        {
            float gi, gf, gg, go;
            up2(gi, gf, s_if0); up2(gg, go, s_go0);
            c0 = fmaf(gf, c0, gi * gg);            // faithful: no sigmoids
            float h = go * fast_tanh(c0);
            h_sh[g][wb][j][hf * 2 + 0] = h;
            prod0 = h * lw;
        }
        {
            float gi, gf, gg, go;
            up2(gi, gf, s_if1); up2(gg, go, s_go1);
            c1 = fmaf(gf, c1, gi * gg);
            float h = go * fast_tanh(c1);
            h_sh[g][wb][j][hf * 2 + 1] = h;
            prod1 = h * lw;
        }

#pragma unroll
        for (int q = 0; q < NBG; q++) xq[q] = xn[q];

        group_bar(g + 1);   // the ONLY barrier per step

        // ---- output reduction AFTER the bar: overlaps next step's phase A ----
        prod0 += __shfl_xor_sync(0xffffffffu, prod0, 1);
        prod1 += __shfl_xor_sync(0xffffffffu, prod1, 1);
        prod0 += __shfl_xor_sync(0xffffffffu, prod0, 2);
        prod1 += __shfl_xor_sync(0xffffffffu, prod1, 2);
        prod0 += __shfl_xor_sync(0xffffffffu, prod0, 4);
        prod1 += __shfl_xor_sync(0xffffffffu, prod1, 4);
        prod0 += __shfl_xor_sync(0xffffffffu, prod0, 8);
        prod1 += __shfl_xor_sync(0xffffffffu, prod1, 8);
        if (j16 == 0) {
            redp[g][t & 1][w][hf * 2 + 0] = prod0;
            redp[g][t & 1][w][hf * 2 + 1] = prod1;
        }
    }

    // ---- tail: one bar to order the last redp writes, then flush t = L-2, L-1 ----
    group_bar(g + 1);
    if (gtid < NBG) {
        int b = gtid;
        {
            int pb = (L_SEQ - 2) & 1;
            out[(b0 + b) * L_SEQ + (L_SEQ - 2)] =
                redp[g][pb][0][b] + redp[g][pb][1][b] +
                redp[g][pb][2][b] + redp[g][pb][3][b] + lbv;
        }
        {
            int pb = (L_SEQ - 1) & 1;
            out[(b0 + b) * L_SEQ + (L_SEQ - 1)] =
                redp[g][pb][0][b] + redp[g][pb][1][b] +
                redp[g][pb][2][b] + redp[g][pb][3][b] + lbv;
        }
    }
}

extern "C" void kernel_launch(void* const* d_in, const int* in_sizes, int n_in,
                              void* d_out, int out_size) {
    (void)in_sizes; (void)n_in; (void)out_size;
    const float* x     = (const float*)d_in[0];
    const float* W_w   = (const float*)d_in[1];
    const float* W_b   = (const float*)d_in[2];
    const float* U_w   = (const float*)d_in[3];
    const float* U_b   = (const float*)d_in[4];
    const float* lin_w = (const float*)d_in[5];
    const float* lin_b = (const float*)d_in[6];
    // d_in[7] = future (static 0) — ignored.

    prep_kernel<<<26, 128>>>(W_w, W_b, U_w, U_b, lin_w);
    lstm_main<<<NBLK, THREADS>>>(x, lin_b, (float*)d_out);
}